// round 7
// baseline (speedup 1.0000x reference)
#include <cuda_runtime.h>
#include <cuda_bf16.h>

// Problem constants
#define B_  8
#define T_  32
#define S_  512
#define F_  128
#define K_  64
#define N_  200

// Tiling
#define SI  32          // s-tile
#define FI  8           // f-tile
#define NT  128         // threads per block (4 warps)
#define NP  8           // t-pairs per thread (16 t's = one half)

// SMEM (bytes):
//   attnF: K*T floats                = 8192
//   stgU:  (T/2)*SI*10 ull           = 40960   (pad 10 -> 16B-aligned reads)
#define SMEM_ATTN_BYTES  (K_*T_*4)
#define SMEM_STG_BYTES   ((T_/2)*SI*10*8)
#define SMEM_TOTAL       (SMEM_ATTN_BYTES + SMEM_STG_BYTES)

typedef unsigned long long ull;

// Packed f32x2 FMA: acc = v * a + acc   (lanes = two adjacent t's)
__device__ __forceinline__ void fma2(ull& acc, ull v, ull a) {
    asm("fma.rn.f32x2 %0, %1, %2, %0;" : "+l"(acc) : "l"(v), "l"(a));
}
// Duplicate one fp32 into both lanes of an f32x2 register pair.
__device__ __forceinline__ ull dup2(float w) {
    ull r;
    asm("mov.b64 %0, {%1, %1};" : "=l"(r) : "f"(w));
    return r;
}

// ---------------------------------------------------------------------------
// Grid: (S/SI, F/FI, B) = (16,16,8) = 2048 blocks, 128 threads, 4 CTAs/SM.
// Thread (sg, fl, tq): 4 s x 1 f x 16 t (8 f32x2 t-pairs).
// V is read straight from global (LDG.128); the tq-partner warp hits L1D.
// ---------------------------------------------------------------------------
__global__ void __launch_bounds__(NT, 4)
fusion_kernel(const float* __restrict__ tgt,
              const float* __restrict__ V,
              const float* __restrict__ corr,
              const int*   __restrict__ tIdx,
              const int*   __restrict__ rIdx,
              float* __restrict__ out) {
    extern __shared__ char smem[];
    float* attnF = (float*)smem;                              // [K][T]
    ull*   stgU  = (ull*)(smem + SMEM_ATTN_BYTES);            // [T/2][SI][10]

    const int b   = blockIdx.z;
    const int f0  = blockIdx.y * FI;
    const int s0  = blockIdx.x * SI;
    const int tid = threadIdx.x;
    const int wid  = tid >> 5;
    const int lane = tid & 31;

    // --- softmax: 4 warps x 8 t's each, gather from L2-hot corr ---
    {
        int c0 = rIdx[lane];
        int c1 = rIdx[lane + 32];
        #pragma unroll
        for (int t = wid; t < T_; t += (NT / 32)) {
            int row = tIdx[b * T_ + t];
            float v0 = __ldg(corr + row * N_ + c0);
            float v1 = __ldg(corr + row * N_ + c1);
            float m = fmaxf(v0, v1);
            #pragma unroll
            for (int off = 16; off > 0; off >>= 1)
                m = fmaxf(m, __shfl_xor_sync(0xffffffffu, m, off));
            float e0 = expf(v0 - m);
            float e1 = expf(v1 - m);
            float s = e0 + e1;
            #pragma unroll
            for (int off = 16; off > 0; off >>= 1)
                s += __shfl_xor_sync(0xffffffffu, s, off);
            float inv = 1.0f / s;
            attnF[lane * T_ + t]        = e0 * inv;
            attnF[(lane + 32) * T_ + t] = e1 * inv;
        }
    }
    __syncthreads();

    // --- main loop: v straight from global, attn broadcast from smem ---
    const int sg = tid & 7;           // 0..7 : s-group (4 s each)
    const int fl = (tid >> 3) & 7;    // 0..7 : f within tile
    const int tq = tid >> 6;          // 0..1 : t-half
    const int t0 = tq * 16;

    const float* vp = V + ((long)b * K_ + 0) * F_ * S_
                        + (long)(f0 + fl) * S_ + s0 + sg * 4;

    ull acc[NP][4];
    #pragma unroll
    for (int p = 0; p < NP; ++p)
        #pragma unroll
        for (int si = 0; si < 4; ++si) acc[p][si] = 0ULL;

    #pragma unroll 4
    for (int k = 0; k < K_; ++k) {
        float4 vf = *(const float4*)(vp + (long)k * F_ * S_);
        ull vd0 = dup2(vf.x), vd1 = dup2(vf.y);
        ull vd2 = dup2(vf.z), vd3 = dup2(vf.w);
        const float* aF = attnF + k * T_ + t0;
        ulonglong2 a01 = *(const ulonglong2*)(aF);
        ulonglong2 a23 = *(const ulonglong2*)(aF + 4);
        ulonglong2 a45 = *(const ulonglong2*)(aF + 8);
        ulonglong2 a67 = *(const ulonglong2*)(aF + 12);
        fma2(acc[0][0], vd0, a01.x); fma2(acc[0][1], vd1, a01.x);
        fma2(acc[0][2], vd2, a01.x); fma2(acc[0][3], vd3, a01.x);
        fma2(acc[1][0], vd0, a01.y); fma2(acc[1][1], vd1, a01.y);
        fma2(acc[1][2], vd2, a01.y); fma2(acc[1][3], vd3, a01.y);
        fma2(acc[2][0], vd0, a23.x); fma2(acc[2][1], vd1, a23.x);
        fma2(acc[2][2], vd2, a23.x); fma2(acc[2][3], vd3, a23.x);
        fma2(acc[3][0], vd0, a23.y); fma2(acc[3][1], vd1, a23.y);
        fma2(acc[3][2], vd2, a23.y); fma2(acc[3][3], vd3, a23.y);
        fma2(acc[4][0], vd0, a45.x); fma2(acc[4][1], vd1, a45.x);
        fma2(acc[4][2], vd2, a45.x); fma2(acc[4][3], vd3, a45.x);
        fma2(acc[5][0], vd0, a45.y); fma2(acc[5][1], vd1, a45.y);
        fma2(acc[5][2], vd2, a45.y); fma2(acc[5][3], vd3, a45.y);
        fma2(acc[6][0], vd0, a67.x); fma2(acc[6][1], vd1, a67.x);
        fma2(acc[6][2], vd2, a67.x); fma2(acc[6][3], vd3, a67.x);
        fma2(acc[7][0], vd0, a67.y); fma2(acc[7][1], vd1, a67.y);
        fma2(acc[7][2], vd2, a67.y); fma2(acc[7][3], vd3, a67.y);
    }
    __syncthreads();   // attnF reads done (stg does not overlay it, but keep order)

    // --- stage: stgU[tpair][s][10] (fl at 0..7, 2 pad) ---
    #pragma unroll
    for (int p = 0; p < NP; ++p) {
        int tp = tq * NP + p;
        #pragma unroll
        for (int si = 0; si < 4; ++si) {
            int s = sg * 4 + si;
            stgU[(tp * SI + s) * 10 + fl] = acc[p][si];
        }
    }
    __syncthreads();

    // --- epilogue: per iter read 4 ull (2 x LDS.128) -> two float4 RMW ---
    // i -> (g, s, tp): g = half of the 8-f row
    #pragma unroll
    for (int i = tid; i < (T_ / 2) * SI * 2; i += NT) {
        int g  = i & 1;
        int s  = (i >> 1) & (SI - 1);
        int tp = i >> 6;
        const ull* src = &stgU[(tp * SI + s) * 10 + 4 * g];
        ulonglong2 u0 = *(const ulonglong2*)(src);       // f = 4g, 4g+1
        ulonglong2 u1 = *(const ulonglong2*)(src + 2);   // f = 4g+2, 4g+3
        float2 p0 = *(const float2*)&u0.x;  // (t_even, t_odd) for f=4g
        float2 p1 = *(const float2*)&u0.y;
        float2 p2 = *(const float2*)&u1.x;
        float2 p3 = *(const float2*)&u1.y;

        long gi0 = (((long)b * T_ + 2 * tp)     * S_ + s0 + s) * F_ + f0 + 4 * g;
        long gi1 = (((long)b * T_ + 2 * tp + 1) * S_ + s0 + s) * F_ + f0 + 4 * g;
        float4 t4, c4;
        t4 = *(const float4*)(tgt + gi0);
        c4.x = p0.x + t4.x; c4.y = p1.x + t4.y;
        c4.z = p2.x + t4.z; c4.w = p3.x + t4.w;
        *(float4*)(out + gi0) = c4;
        t4 = *(const float4*)(tgt + gi1);
        c4.x = p0.y + t4.x; c4.y = p1.y + t4.y;
        c4.z = p2.y + t4.z; c4.w = p3.y + t4.w;
        *(float4*)(out + gi1) = c4;
    }
}

// ---------------------------------------------------------------------------
extern "C" void kernel_launch(void* const* d_in, const int* in_sizes, int n_in,
                              void* d_out, int out_size) {
    const float* tgt  = nullptr;   // 16777216
    const float* V    = nullptr;   // 33554432
    const float* corr = nullptr;   // 40000
    const int*   tIdx = nullptr;   // 256   (int32: jax x64 disabled)
    const int*   rIdx = nullptr;   // 64

    for (int i = 0; i < n_in; ++i) {
        switch (in_sizes[i]) {
            case 16777216: tgt  = (const float*)d_in[i]; break;
            case 33554432: V    = (const float*)d_in[i]; break;
            case 40000:    corr = (const float*)d_in[i]; break;
            case 256:      tIdx = (const int*)d_in[i]; break;
            case 64:       rIdx = (const int*)d_in[i]; break;
            default: break;
        }
    }

    cudaFuncSetAttribute(fusion_kernel,
                         cudaFuncAttributeMaxDynamicSharedMemorySize,
                         SMEM_TOTAL);

    dim3 grid(S_ / SI, F_ / FI, B_);
    fusion_kernel<<<grid, NT, SMEM_TOTAL>>>(tgt, V, corr, tIdx, rIdx, (float*)d_out);
}

// round 9
// speedup vs baseline: 1.1962x; 1.1962x over previous
#include <cuda_runtime.h>
#include <cuda_bf16.h>

// Problem constants
#define B_  8
#define T_  32
#define S_  512
#define F_  128
#define K_  64
#define N_  200

// Tiling
#define SI  32          // s-tile
#define FI  8           // f-tile
#define NT  256         // threads per block (8 warps)
#define KC  16          // k's per pipeline chunk
#define NCHUNK (K_/KC)  // 4
#define NP  4           // t-pairs per thread (8 t's per quadrant)

// SMEM (bytes):
//   Vbuf:  2 x KC*FI*SI floats = 2 x 16384 = 32768 (double buffer)
//   attnF: K*T floats          = 8192
//   stgU:  (T/2)*SI*10 ull     = 40960  (overlays everything after the loop)
#define SMEM_VBUF_BYTES  (KC*FI*SI*4)
#define SMEM_ATTN_BYTES  (K_*T_*4)
#define SMEM_TOTAL       (2*SMEM_VBUF_BYTES + SMEM_ATTN_BYTES)

typedef unsigned long long ull;

// Packed f32x2 FMA: acc = v * a + acc   (lanes = two adjacent t's)
__device__ __forceinline__ void fma2(ull& acc, ull v, ull a) {
    asm("fma.rn.f32x2 %0, %1, %2, %0;" : "+l"(acc) : "l"(v), "l"(a));
}
// Duplicate one fp32 into both lanes of an f32x2 register pair.
__device__ __forceinline__ ull dup2(float w) {
    ull r;
    asm("mov.b64 %0, {%1, %1};" : "=l"(r) : "f"(w));
    return r;
}
// 16B async copy global -> shared
__device__ __forceinline__ void cp_async16(float* smem_dst, const float* gsrc) {
    unsigned s = (unsigned)__cvta_generic_to_shared(smem_dst);
    asm volatile("cp.async.cg.shared.global [%0], [%1], 16;" :: "r"(s), "l"(gsrc));
}
__device__ __forceinline__ void cp_commit() {
    asm volatile("cp.async.commit_group;");
}
template <int N>
__device__ __forceinline__ void cp_wait() {
    asm volatile("cp.async.wait_group %0;" :: "n"(N));
}

// ---------------------------------------------------------------------------
// Grid: (S/SI, F/FI, B) = (16,16,8) = 2048 blocks, 256 threads, 3 CTAs/SM.
// Thread (sg, fl, tq): 4 s x 1 f x 8 t (4 f32x2 t-pairs).
// ---------------------------------------------------------------------------
__global__ void __launch_bounds__(NT, 3)
fusion_kernel(const float* __restrict__ tgt,
              const float* __restrict__ V,
              const float* __restrict__ corr,
              const int*   __restrict__ tIdx,
              const int*   __restrict__ rIdx,
              float* __restrict__ out) {
    extern __shared__ char smem[];
    float* Vb[2] = { (float*)smem, (float*)(smem + SMEM_VBUF_BYTES) };
    float* attnF = (float*)(smem + 2 * SMEM_VBUF_BYTES);   // [K][T]
    ull*   stgU  = (ull*)smem;                              // overlay after loop

    const int b   = blockIdx.z;
    const int f0  = blockIdx.y * FI;
    const int s0  = blockIdx.x * SI;
    const int tid = threadIdx.x;
    const int wid  = tid >> 5;
    const int lane = tid & 31;

    const float* Vg = V + (long)b * K_ * F_ * S_ + (long)f0 * S_ + s0;

    // --- prefetch chunk 0 (latency hidden under softmax) ---
    {
        #pragma unroll
        for (int i = tid; i < KC * FI * (SI / 4); i += NT) {
            int k  = i / (FI * (SI / 4));
            int f  = (i / (SI / 4)) % FI;
            int s4 = i % (SI / 4);
            cp_async16(Vb[0] + (k * FI + f) * SI + s4 * 4,
                       Vg + ((long)k * F_ + f) * S_ + s4 * 4);
        }
        cp_commit();
    }

    // --- softmax: 8 warps x 4 t's each ---
    {
        int c0 = rIdx[lane];
        int c1 = rIdx[lane + 32];
        #pragma unroll
        for (int t = wid; t < T_; t += (NT / 32)) {
            int row = tIdx[b * T_ + t];
            float v0 = __ldg(corr + row * N_ + c0);
            float v1 = __ldg(corr + row * N_ + c1);
            float m = fmaxf(v0, v1);
            #pragma unroll
            for (int off = 16; off > 0; off >>= 1)
                m = fmaxf(m, __shfl_xor_sync(0xffffffffu, m, off));
            float e0 = expf(v0 - m);
            float e1 = expf(v1 - m);
            float s = e0 + e1;
            #pragma unroll
            for (int off = 16; off > 0; off >>= 1)
                s += __shfl_xor_sync(0xffffffffu, s, off);
            float inv = 1.0f / s;
            attnF[lane * T_ + t]        = e0 * inv;
            attnF[(lane + 32) * T_ + t] = e1 * inv;
        }
    }

    // --- main loop: double-buffered k-chunks ---
    const int sg = tid & 7;           // 0..7 : s-group (4 s each)
    const int fl = (tid >> 3) & 7;    // 0..7 : f within tile
    const int tq = tid >> 6;          // 0..3 : t-quadrant
    const int t0 = tq * 8;

    ull acc[NP][4];
    #pragma unroll
    for (int p = 0; p < NP; ++p)
        #pragma unroll
        for (int si = 0; si < 4; ++si) acc[p][si] = 0ULL;

    #pragma unroll
    for (int c = 0; c < NCHUNK; ++c) {
        if (c + 1 < NCHUNK) {
            float* dst = Vb[(c + 1) & 1];
            const float* src = Vg + (long)(c + 1) * KC * F_ * S_;
            #pragma unroll
            for (int i = tid; i < KC * FI * (SI / 4); i += NT) {
                int k  = i / (FI * (SI / 4));
                int f  = (i / (SI / 4)) % FI;
                int s4 = i % (SI / 4);
                cp_async16(dst + (k * FI + f) * SI + s4 * 4,
                           src + ((long)k * F_ + f) * S_ + s4 * 4);
            }
            cp_commit();
            cp_wait<1>();   // chunk c resident
        } else {
            cp_wait<0>();
        }
        __syncthreads();    // publishes chunk (and attnF on c==0)

        const float* Vc = Vb[c & 1];
        const float* aF = attnF + c * KC * T_;
        #pragma unroll 4
        for (int k = 0; k < KC; ++k) {
            float4 vf = *(const float4*)(Vc + (k * FI + fl) * SI + sg * 4);
            ull vd0 = dup2(vf.x), vd1 = dup2(vf.y);
            ull vd2 = dup2(vf.z), vd3 = dup2(vf.w);
            // attn t-pairs, non-duplicated, broadcast loads (8 t's)
            ulonglong2 a01 = *(const ulonglong2*)(aF + k * T_ + t0);
            ulonglong2 a23 = *(const ulonglong2*)(aF + k * T_ + t0 + 4);
            fma2(acc[0][0], vd0, a01.x); fma2(acc[0][1], vd1, a01.x);
            fma2(acc[0][2], vd2, a01.x); fma2(acc[0][3], vd3, a01.x);
            fma2(acc[1][0], vd0, a01.y); fma2(acc[1][1], vd1, a01.y);
            fma2(acc[1][2], vd2, a01.y); fma2(acc[1][3], vd3, a01.y);
            fma2(acc[2][0], vd0, a23.x); fma2(acc[2][1], vd1, a23.x);
            fma2(acc[2][2], vd2, a23.x); fma2(acc[2][3], vd3, a23.x);
            fma2(acc[3][0], vd0, a23.y); fma2(acc[3][1], vd1, a23.y);
            fma2(acc[3][2], vd2, a23.y); fma2(acc[3][3], vd3, a23.y);
        }
        __syncthreads();    // all reads of buf (c&1) done before refill
    }

    // --- stage: stgU[tpair][s][10] (fl at 0..7, 2 pad); overlays V buffers ---
    #pragma unroll
    for (int p = 0; p < NP; ++p) {
        int tp = tq * NP + p;
        #pragma unroll
        for (int si = 0; si < 4; ++si) {
            int s = sg * 4 + si;
            stgU[(tp * SI + s) * 10 + fl] = acc[p][si];
        }
    }
    __syncthreads();

    // --- epilogue: per iter read 4 ull (2 x LDS.128) -> two float4 RMW ---
    #pragma unroll
    for (int i = tid; i < (T_ / 2) * SI * 2; i += NT) {
        int g  = i & 1;
        int s  = (i >> 1) & (SI - 1);
        int tp = i >> 6;
        const ull* src = &stgU[(tp * SI + s) * 10 + 4 * g];
        ulonglong2 u0 = *(const ulonglong2*)(src);       // f = 4g, 4g+1
        ulonglong2 u1 = *(const ulonglong2*)(src + 2);   // f = 4g+2, 4g+3
        float2 p0 = *(const float2*)&u0.x;  // (t_even, t_odd)
        float2 p1 = *(const float2*)&u0.y;
        float2 p2 = *(const float2*)&u1.x;
        float2 p3 = *(const float2*)&u1.y;

        long gi0 = (((long)b * T_ + 2 * tp)     * S_ + s0 + s) * F_ + f0 + 4 * g;
        long gi1 = (((long)b * T_ + 2 * tp + 1) * S_ + s0 + s) * F_ + f0 + 4 * g;
        float4 t4, c4;
        t4 = *(const float4*)(tgt + gi0);
        c4.x = p0.x + t4.x; c4.y = p1.x + t4.y;
        c4.z = p2.x + t4.z; c4.w = p3.x + t4.w;
        *(float4*)(out + gi0) = c4;
        t4 = *(const float4*)(tgt + gi1);
        c4.x = p0.y + t4.x; c4.y = p1.y + t4.y;
        c4.z = p2.y + t4.z; c4.w = p3.y + t4.w;
        *(float4*)(out + gi1) = c4;
    }
}

// ---------------------------------------------------------------------------
extern "C" void kernel_launch(void* const* d_in, const int* in_sizes, int n_in,
                              void* d_out, int out_size) {
    const float* tgt  = nullptr;   // 16777216
    const float* V    = nullptr;   // 33554432
    const float* corr = nullptr;   // 40000
    const int*   tIdx = nullptr;   // 256   (int32: jax x64 disabled)
    const int*   rIdx = nullptr;   // 64

    for (int i = 0; i < n_in; ++i) {
        switch (in_sizes[i]) {
            case 16777216: tgt  = (const float*)d_in[i]; break;
            case 33554432: V    = (const float*)d_in[i]; break;
            case 40000:    corr = (const float*)d_in[i]; break;
            case 256:      tIdx = (const int*)d_in[i]; break;
            case 64:       rIdx = (const int*)d_in[i]; break;
            default: break;
        }
    }

    cudaFuncSetAttribute(fusion_kernel,
                         cudaFuncAttributeMaxDynamicSharedMemorySize,
                         SMEM_TOTAL);

    dim3 grid(S_ / SI, F_ / FI, B_);
    fusion_kernel<<<grid, NT, SMEM_TOTAL>>>(tgt, V, corr, tIdx, rIdx, (float*)d_out);
}